// round 10
// baseline (speedup 1.0000x reference)
#include <cuda_runtime.h>
#include <cuda_bf16.h>

#define N_WAVES 128
#define POLYN 40                 // top-POLYN waves by freq -> exact-reduction poly path
#define RAWN (N_WAVES - POLYN)   // 88 low-freq waves -> raw-radian MUFU path
#define TPB 128

__device__ __forceinline__ float sinap(float a) {
    float r; asm("sin.approx.f32 %0, %1;" : "=f"(r) : "f"(a)); return r;
}

// sin(pi*d), d in [-0.5, 0.5]: degree-7 odd minimax, coeffs folded to d-domain
#define A1F  3.14158197f
#define A3F -5.16714000f
#define A5F  2.54189000f
#define A7F -0.55461700f
#define MAGF 12582912.f          // 1.5 * 2^23

__global__ void __launch_bounds__(TPB, 12)
wave_kernel(const float4* __restrict__ x4,   // 2 points per float4
            const float* __restrict__ freqs,
            const float* __restrict__ rots,
            const float* __restrict__ coeffs,
            float2* __restrict__ out2, int n) {
    // Slots [0, RAWN): low-freq waves, params (gx,gy,ph,A) in RADIANS.
    // Slots [RAWN, 128): top-POLYN-by-freq waves, params in HALF-CYCLES (v=2u).
    __shared__ float sf[N_WAVES];
    __shared__ float4 swp[N_WAVES];

    int w = threadIdx.x;
    float fw = 0.f;
    if (w < N_WAVES) { fw = freqs[w]; sf[w] = fw; }
    __syncthreads();

    if (w < N_WAVES) {
        // Deterministic rank (descending freq, tie-break by index).
        int rank = 0;
        for (int j = 0; j < N_WAVES; j++) {
            float fj = sf[j];
            rank += (fj > fw) || (fj == fw && j < w);
        }
        bool isPoly = (rank < POLYN);
        int slot = isPoly ? (RAWN + rank) : (rank - POLYN);

        float r  = rots[w];
        float c0 = coeffs[2 * w];
        float c1 = coeffs[2 * w + 1];
        float sr, cr;
        sincosf(r, &sr, &cr);
        float A  = sqrtf(c0 * c0 + c1 * c1);
        float ph = atan2f(c1, c0);            // radians
        float gx, gy, p0;
        if (isPoly) {                          // half-cycle domain
            gx = 2.f * fw * cr;
            gy = 2.f * fw * sr;
            p0 = ph * 0.3183098861837907f;     // ph / pi
        } else {                               // raw radian domain
            const float two_pi = 6.283185307179586f;
            gx = two_pi * fw * cr;
            gy = two_pi * fw * sr;
            p0 = ph;
        }
        swp[slot] = make_float4(gx, gy, p0, A);
    }
    __syncthreads();

    int pairsTotal = n >> 1;
    int p = blockIdx.x * TPB + threadIdx.x;   // one float4 (pair of points) per thread

    float4 a = (p < pairsTotal) ? x4[p] : make_float4(0.f, 0.f, 0.f, 0.f);
    float x0 = a.x, y0 = a.y, x1 = a.z, y1 = a.w;
    float acc0 = 0.f, acc1 = 0.f;

    // Single interleaved loop: each iteration issues one MUFU-path wave and
    // (for i < POLYN) one FMA-pipe poly wave, overlapping both pipes.
#pragma unroll 4
    for (int i = 0; i < RAWN; i++) {
        {   // raw-radian MUFU wave
            float4 q = swp[i];
            float u0 = fmaf(x0, q.x, fmaf(y0, q.y, q.z));
            float u1 = fmaf(x1, q.x, fmaf(y1, q.y, q.z));
            acc0 = fmaf(q.w, sinap(u0), acc0);
            acc1 = fmaf(q.w, sinap(u1), acc1);
        }
        if (i < POLYN) {  // exact-reduction polynomial wave (FMA pipe)
            float4 q = swp[RAWN + i];
            float v0 = fmaf(x0, q.x, fmaf(y0, q.y, q.z));
            float v1 = fmaf(x1, q.x, fmaf(y1, q.y, q.z));
            float t0 = v0 + MAGF, t1 = v1 + MAGF;     // bit0 = parity of rint(v)
            float n0 = t0 - MAGF, n1 = t1 - MAGF;     // rint(v)
            float d0 = v0 - n0,  d1 = v1 - n1;        // [-0.5, 0.5]
            float s0 = d0 * d0,  s1 = d1 * d1;
            float p0 = fmaf(A7F, s0, A5F), p1 = fmaf(A7F, s1, A5F);
            p0 = fmaf(p0, s0, A3F); p1 = fmaf(p1, s1, A3F);
            p0 = fmaf(p0, s0, A1F); p1 = fmaf(p1, s1, A1F);
            float r0 = p0 * d0, r1 = p1 * d1;         // sin(pi*d)
            r0 = __uint_as_float(__float_as_uint(r0) ^ (__float_as_uint(t0) << 31));
            r1 = __uint_as_float(__float_as_uint(r1) ^ (__float_as_uint(t1) << 31));
            acc0 = fmaf(q.w, r0, acc0);
            acc1 = fmaf(q.w, r1, acc1);
        }
    }

    if (p < pairsTotal) out2[p] = make_float2(acc0, acc1);

    // Odd-n tail: single scalar point.
    if ((n & 1) && blockIdx.x == 0 && threadIdx.x == 0) {
        float tx = ((const float2*)x4)[n - 1].x;
        float ty = ((const float2*)x4)[n - 1].y;
        float ac = 0.f;
        for (int i = 0; i < N_WAVES; i++) {
            float4 q = swp[i];
            if (i < RAWN) {                    // radian params, low freq
                float u = fmaf(tx, q.x, fmaf(ty, q.y, q.z));
                ac = fmaf(q.w, sinap(u), ac);
            } else {                           // half-cycle params
                float v = fmaf(tx, q.x, fmaf(ty, q.y, q.z));
                float nn = rintf(v);
                float d = v - nn;
                float sv = sinap(3.14159265f * d);
                if (((int)nn) & 1) sv = -sv;
                ac = fmaf(q.w, sv, ac);
            }
        }
        ((float*)out2)[n - 1] = ac;
    }
}

extern "C" void kernel_launch(void* const* d_in, const int* in_sizes, int n_in,
                              void* d_out, int out_size) {
    const float* x      = (const float*)d_in[0];  // [N,2]
    const float* freqs  = (const float*)d_in[1];  // [W,1]
    const float* rots   = (const float*)d_in[2];  // [W,1]
    const float* coeffs = (const float*)d_in[3];  // [W,2]
    float* out = (float*)d_out;                   // [N,1]

    int n = in_sizes[0] / 2;

    int pairs = (n + 1) / 2;
    int blocks = (pairs + TPB - 1) / TPB;
    wave_kernel<<<blocks, TPB>>>((const float4*)x, freqs, rots, coeffs,
                                 (float2*)out, n);
}

// round 11
// speedup vs baseline: 1.0692x; 1.0692x over previous
#include <cuda_runtime.h>
#include <cuda_bf16.h>

#define N_WAVES 128
#define POLYN 24                 // top-POLYN waves by freq -> exact-reduction poly path
#define RAWN (N_WAVES - POLYN)   // 104 low-freq waves -> raw-radian MUFU path
#define TPB 128

__device__ __forceinline__ float sinap(float a) {
    float r; asm("sin.approx.f32 %0, %1;" : "=f"(r) : "f"(a)); return r;
}

// sin(pi*d), d in [-0.5, 0.5]: degree-7 odd minimax, coeffs folded to d-domain
#define A1F  3.14158197f
#define A3F -5.16714000f
#define A5F  2.54189000f
#define A7F -0.55461700f
#define MAGF 12582912.f          // 1.5 * 2^23

__global__ void __launch_bounds__(TPB, 16)
wave_kernel(const float4* __restrict__ x4,   // 2 points per float4
            const float* __restrict__ freqs,
            const float* __restrict__ rots,
            const float* __restrict__ coeffs,
            float2* __restrict__ out2, int n) {
    // Slots [0, RAWN): low-freq waves, params (gx,gy,ph,A) in RADIANS.
    // Slots [RAWN, 128): top-POLYN-by-freq waves, params in HALF-CYCLES (v=2u).
    __shared__ float sf[N_WAVES];
    __shared__ float4 swp[N_WAVES];

    int w = threadIdx.x;
    float fw = 0.f;
    if (w < N_WAVES) { fw = freqs[w]; sf[w] = fw; }
    __syncthreads();

    if (w < N_WAVES) {
        // Deterministic rank (descending freq, tie-break by index).
        int rank = 0;
        for (int j = 0; j < N_WAVES; j++) {
            float fj = sf[j];
            rank += (fj > fw) || (fj == fw && j < w);
        }
        bool isPoly = (rank < POLYN);
        int slot = isPoly ? (RAWN + rank) : (rank - POLYN);

        float r  = rots[w];
        float c0 = coeffs[2 * w];
        float c1 = coeffs[2 * w + 1];
        float sr, cr;
        sincosf(r, &sr, &cr);
        float A  = sqrtf(c0 * c0 + c1 * c1);
        float ph = atan2f(c1, c0);            // radians
        float gx, gy, p0;
        if (isPoly) {                          // half-cycle domain
            gx = 2.f * fw * cr;
            gy = 2.f * fw * sr;
            p0 = ph * 0.3183098861837907f;     // ph / pi
        } else {                               // raw radian domain
            const float two_pi = 6.283185307179586f;
            gx = two_pi * fw * cr;
            gy = two_pi * fw * sr;
            p0 = ph;
        }
        swp[slot] = make_float4(gx, gy, p0, A);
    }
    __syncthreads();

    int pairsTotal = n >> 1;
    int p = blockIdx.x * TPB + threadIdx.x;   // one float4 (pair of points) per thread

    float4 a = (p < pairsTotal) ? x4[p] : make_float4(0.f, 0.f, 0.f, 0.f);
    float x0 = a.x, y0 = a.y, x1 = a.z, y1 = a.w;
    float acc0 = 0.f, acc1 = 0.f;

    // Interleaved loop: each iteration issues one MUFU-path wave plus (for
    // i < POLYN) one FMA-pipe poly wave, so both pipes stay fed concurrently.
#pragma unroll 4
    for (int i = 0; i < RAWN; i++) {
        {   // raw-radian MUFU wave
            float4 q = swp[i];
            float u0 = fmaf(x0, q.x, fmaf(y0, q.y, q.z));
            float u1 = fmaf(x1, q.x, fmaf(y1, q.y, q.z));
            acc0 = fmaf(q.w, sinap(u0), acc0);
            acc1 = fmaf(q.w, sinap(u1), acc1);
        }
        if (i < POLYN) {  // exact-reduction polynomial wave (FMA pipe)
            float4 q = swp[RAWN + i];
            float v0 = fmaf(x0, q.x, fmaf(y0, q.y, q.z));
            float v1 = fmaf(x1, q.x, fmaf(y1, q.y, q.z));
            float t0 = v0 + MAGF, t1 = v1 + MAGF;     // bit0 = parity of rint(v)
            float n0 = t0 - MAGF, n1 = t1 - MAGF;     // rint(v)
            float d0 = v0 - n0,  d1 = v1 - n1;        // [-0.5, 0.5]
            float s0 = d0 * d0,  s1 = d1 * d1;
            float p0 = fmaf(A7F, s0, A5F), p1 = fmaf(A7F, s1, A5F);
            p0 = fmaf(p0, s0, A3F); p1 = fmaf(p1, s1, A3F);
            p0 = fmaf(p0, s0, A1F); p1 = fmaf(p1, s1, A1F);
            float r0 = p0 * d0, r1 = p1 * d1;         // sin(pi*d)
            r0 = __uint_as_float(__float_as_uint(r0) ^ (__float_as_uint(t0) << 31));
            r1 = __uint_as_float(__float_as_uint(r1) ^ (__float_as_uint(t1) << 31));
            acc0 = fmaf(q.w, r0, acc0);
            acc1 = fmaf(q.w, r1, acc1);
        }
    }

    if (p < pairsTotal) out2[p] = make_float2(acc0, acc1);

    // Odd-n tail: single scalar point.
    if ((n & 1) && blockIdx.x == 0 && threadIdx.x == 0) {
        float tx = ((const float2*)x4)[n - 1].x;
        float ty = ((const float2*)x4)[n - 1].y;
        float ac = 0.f;
        for (int i = 0; i < N_WAVES; i++) {
            float4 q = swp[i];
            if (i < RAWN) {                    // radian params, low freq
                float u = fmaf(tx, q.x, fmaf(ty, q.y, q.z));
                ac = fmaf(q.w, sinap(u), ac);
            } else {                           // half-cycle params
                float v = fmaf(tx, q.x, fmaf(ty, q.y, q.z));
                float nn = rintf(v);
                float d = v - nn;
                float sv = sinap(3.14159265f * d);
                if (((int)nn) & 1) sv = -sv;
                ac = fmaf(q.w, sv, ac);
            }
        }
        ((float*)out2)[n - 1] = ac;
    }
}

extern "C" void kernel_launch(void* const* d_in, const int* in_sizes, int n_in,
                              void* d_out, int out_size) {
    const float* x      = (const float*)d_in[0];  // [N,2]
    const float* freqs  = (const float*)d_in[1];  // [W,1]
    const float* rots   = (const float*)d_in[2];  // [W,1]
    const float* coeffs = (const float*)d_in[3];  // [W,2]
    float* out = (float*)d_out;                   // [N,1]

    int n = in_sizes[0] / 2;

    int pairs = (n + 1) / 2;
    int blocks = (pairs + TPB - 1) / TPB;
    wave_kernel<<<blocks, TPB>>>((const float4*)x, freqs, rots, coeffs,
                                 (float2*)out, n);
}

// round 12
// speedup vs baseline: 1.2423x; 1.1620x over previous
#include <cuda_runtime.h>
#include <cuda_bf16.h>

#define N_WAVES 128
#define POLYN 12                 // top-POLYN waves by freq -> exact-reduction poly path
#define RAWN (N_WAVES - POLYN)   // 116 low/mid-freq waves -> raw-radian MUFU path
#define TPB 128

__device__ __forceinline__ float sinap(float a) {
    float r; asm("sin.approx.f32 %0, %1;" : "=f"(r) : "f"(a)); return r;
}

// sin(pi*d), d in [-0.5, 0.5]: degree-7 odd minimax (folded per-wave with A)
#define A1F  3.14158197f
#define A3F -5.16714000f
#define A5F  2.54189000f
#define A7F -0.55461700f
#define MAGF 12582912.f          // 1.5 * 2^23

__global__ void __launch_bounds__(TPB, 8)
wave_kernel(const float4* __restrict__ x4,   // 2 points per float4
            const float* __restrict__ freqs,
            const float* __restrict__ rots,
            const float* __restrict__ coeffs,
            float2* __restrict__ out2, int n) {
    // Slots [0, RAWN): raw-radian MUFU waves: swp = (gx,gy,ph,A) in radians.
    // Slots [RAWN,128): poly waves: swp = (gx,gy,ph,unused) in HALF-CYCLES,
    //                   spoly = A-folded poly coeffs (A*A1, A*A3, A*A5, A*A7).
    __shared__ float sf[N_WAVES];
    __shared__ float4 swp[N_WAVES];
    __shared__ float4 spoly[POLYN];

    int w = threadIdx.x;
    float fw = 0.f;
    if (w < N_WAVES) { fw = freqs[w]; sf[w] = fw; }
    __syncthreads();

    if (w < N_WAVES) {
        // Deterministic rank (descending freq, tie-break by index).
        int rank = 0;
        for (int j = 0; j < N_WAVES; j++) {
            float fj = sf[j];
            rank += (fj > fw) || (fj == fw && j < w);
        }
        bool isPoly = (rank < POLYN);

        float r  = rots[w];
        float c0 = coeffs[2 * w];
        float c1 = coeffs[2 * w + 1];
        float sr, cr;
        sincosf(r, &sr, &cr);
        float A  = sqrtf(c0 * c0 + c1 * c1);
        float ph = atan2f(c1, c0);            // radians
        if (isPoly) {                          // half-cycle domain, A folded into coeffs
            int slot = RAWN + rank;
            swp[slot] = make_float4(2.f * fw * cr, 2.f * fw * sr,
                                    ph * 0.3183098861837907f, 0.f);
            spoly[rank] = make_float4(A * A1F, A * A3F, A * A5F, A * A7F);
        } else {                               // raw radian domain
            const float two_pi = 6.283185307179586f;
            swp[rank - POLYN] = make_float4(two_pi * fw * cr, two_pi * fw * sr, ph, A);
        }
    }
    __syncthreads();

    int pairsTotal = n >> 1;
    int pA = blockIdx.x * (2 * TPB) + threadIdx.x;   // float4 index, pair 1
    int pB = pA + TPB;                               // float4 index, pair 2

    float4 a = (pA < pairsTotal) ? x4[pA] : make_float4(0.f, 0.f, 0.f, 0.f);
    float4 b = (pB < pairsTotal) ? x4[pB] : make_float4(0.f, 0.f, 0.f, 0.f);
    float x0 = a.x, y0 = a.y, x1 = a.z, y1 = a.w;
    float x2 = b.x, y2 = b.y, x3 = b.z, y3 = b.w;
    float acc0 = 0.f, acc1 = 0.f, acc2 = 0.f, acc3 = 0.f;

    // ---- raw-radian MUFU waves: 3 FFMA + 1 MUFU per point per wave ----
#pragma unroll 4
    for (int i = 0; i < RAWN; i++) {
        float4 q = swp[i];
        float u0 = fmaf(x0, q.x, fmaf(y0, q.y, q.z));
        float u1 = fmaf(x1, q.x, fmaf(y1, q.y, q.z));
        float u2 = fmaf(x2, q.x, fmaf(y2, q.y, q.z));
        float u3 = fmaf(x3, q.x, fmaf(y3, q.y, q.z));
        acc0 = fmaf(q.w, sinap(u0), acc0);
        acc1 = fmaf(q.w, sinap(u1), acc1);
        acc2 = fmaf(q.w, sinap(u2), acc2);
        acc3 = fmaf(q.w, sinap(u3), acc3);
    }

    // ---- poly waves: exact half-cycle reduction, A-folded coeffs ----
#pragma unroll
    for (int i = 0; i < POLYN; i++) {
        float4 q = swp[RAWN + i];
        float4 c = spoly[i];
#pragma unroll
        for (int j = 0; j < 4; j++) {
            float xx = (j == 0) ? x0 : (j == 1) ? x1 : (j == 2) ? x2 : x3;
            float yy = (j == 0) ? y0 : (j == 1) ? y1 : (j == 2) ? y2 : y3;
            float v = fmaf(xx, q.x, fmaf(yy, q.y, q.z));  // half-cycles
            float t = v + MAGF;               // mantissa bit0 = parity of rint(v)
            float nn = t - MAGF;              // rint(v)
            float d = v - nn;                 // [-0.5, 0.5]
            // sign -> d (ALU pipe), so the poly result needs no extra mul
            d = __uint_as_float(__float_as_uint(d) ^ (__float_as_uint(t) << 31));
            float s = d * d;                  // sign-invariant
            float p = fmaf(c.w, s, c.z);      // A*A7*s + A*A5
            p = fmaf(p, s, c.y);
            p = fmaf(p, s, c.x);              // A * (A1 + A3 s + A5 s^2 + A7 s^3)
            float r = p * d;                  // = A * sin(pi*d) signed
            if (j == 0) acc0 += r; else if (j == 1) acc1 += r;
            else if (j == 2) acc2 += r; else acc3 += r;
        }
    }

    if (pA < pairsTotal) out2[pA] = make_float2(acc0, acc1);
    if (pB < pairsTotal) out2[pB] = make_float2(acc2, acc3);

    // Odd-n tail: single scalar point.
    if ((n & 1) && blockIdx.x == 0 && threadIdx.x == 0) {
        float tx = ((const float2*)x4)[n - 1].x;
        float ty = ((const float2*)x4)[n - 1].y;
        float ac = 0.f;
        for (int i = 0; i < RAWN; i++) {
            float4 q = swp[i];
            float u = fmaf(tx, q.x, fmaf(ty, q.y, q.z));
            ac = fmaf(q.w, sinap(u), ac);
        }
        for (int i = 0; i < POLYN; i++) {
            float4 q = swp[RAWN + i];
            float4 c = spoly[i];
            float v = fmaf(tx, q.x, fmaf(ty, q.y, q.z));
            float nn = rintf(v);
            float d = v - nn;
            if (((int)nn) & 1) d = -d;
            float s = d * d;
            float p = fmaf(c.w, s, c.z);
            p = fmaf(p, s, c.y);
            p = fmaf(p, s, c.x);
            ac = fmaf(p, d, ac);
        }
        ((float*)out2)[n - 1] = ac;
    }
}

extern "C" void kernel_launch(void* const* d_in, const int* in_sizes, int n_in,
                              void* d_out, int out_size) {
    const float* x      = (const float*)d_in[0];  // [N,2]
    const float* freqs  = (const float*)d_in[1];  // [W,1]
    const float* rots   = (const float*)d_in[2];  // [W,1]
    const float* coeffs = (const float*)d_in[3];  // [W,2]
    float* out = (float*)d_out;                   // [N,1]

    int n = in_sizes[0] / 2;

    int pairs = (n + 1) / 2;
    int blocks = (pairs + 2 * TPB - 1) / (2 * TPB);
    wave_kernel<<<blocks, TPB>>>((const float4*)x, freqs, rots, coeffs,
                                 (float2*)out, n);
}